// round 14
// baseline (speedup 1.0000x reference)
#include <cuda_runtime.h>
#include <cuda_bf16.h>
#include <cstdint>

// Problem constants
#define BB 4
#define SQ 4096
#define SK 462
#define SKP 512     // padded
#define HH 10
#define DH 64
#define DD 640

#define QT  64      // q rows per CTA
#define CK  64      // k chunk
#define NCH 8       // chunks (512 padded)
#define NTHREADS 128

#define STR 36      // u32 row stride (rows 144B, 16B-aligned)

// SMEM u32 offsets (six 64x36 buffers)
#define O_QH 0
#define O_QL 2304
#define O_KH 4608
#define O_KL 6912
#define O_VH 9216
#define O_VL 11520
#define SMEM_U32 13824          // 55296 B

#define MNEG (-1e30f)

// Pre-converted bf16 hi/lo buffers, rows permuted into fragment order:
// word w = 8*ss + tig + 4*half  stored at  p = tig*8 + 2*ss + half
__device__ uint32_t g_QH[(size_t)BB*HH*SQ*32];    // [bh][q][32]
__device__ uint32_t g_QL[(size_t)BB*HH*SQ*32];
__device__ uint32_t g_KH[(size_t)BB*HH*SKP*32];   // [bh][kk][32]
__device__ uint32_t g_KL[(size_t)BB*HH*SKP*32];
__device__ uint32_t g_VH[(size_t)BB*HH*DH*256];   // [bh][d][kp] (perm per 32-chunk)
__device__ uint32_t g_VL[(size_t)BB*HH*DH*256];

static __device__ __forceinline__ uint32_t smem_u32(const void* p) {
    uint32_t a;
    asm("{ .reg .u64 t; cvta.to.shared.u64 t, %1; cvt.u32.u64 %0, t; }" : "=r"(a) : "l"(p));
    return a;
}

#define CPA16(dst, src) \
    asm volatile("cp.async.cg.shared.global [%0], [%1], 16;" :: "r"(dst), "l"(src) : "memory")
#define CPA_COMMIT() asm volatile("cp.async.commit_group;" ::: "memory")
#define CPA_WAIT0()  asm volatile("cp.async.wait_group 0;" ::: "memory")

// fragment permutation: w -> p
static __device__ __forceinline__ int fragperm(int w) {
    int ss = w >> 3, rem = w & 7, half = rem >> 2, tig = rem & 3;
    return tig * 8 + ss * 2 + half;
}

static __device__ __forceinline__ void split2(float a, float b,
                                              uint32_t& hi, uint32_t& lo)
{
    __nv_bfloat16 ah = __float2bfloat16_rn(a);
    __nv_bfloat16 bh = __float2bfloat16_rn(b);
    __nv_bfloat16 al = __float2bfloat16_rn(a - __bfloat162float(ah));
    __nv_bfloat16 bl = __float2bfloat16_rn(b - __bfloat162float(bh));
    hi = (uint32_t)__bfloat16_as_ushort(ah) | ((uint32_t)__bfloat16_as_ushort(bh) << 16);
    lo = (uint32_t)__bfloat16_as_ushort(al) | ((uint32_t)__bfloat16_as_ushort(bl) << 16);
}

static __device__ __forceinline__ void mma16816(float* c,
    uint32_t a0, uint32_t a1, uint32_t a2, uint32_t a3, uint32_t b0, uint32_t b1)
{
    asm volatile(
        "mma.sync.aligned.m16n8k16.row.col.f32.bf16.bf16.f32 "
        "{%0,%1,%2,%3}, {%4,%5,%6,%7}, {%8,%9}, {%0,%1,%2,%3};"
        : "+f"(c[0]), "+f"(c[1]), "+f"(c[2]), "+f"(c[3])
        : "r"(a0), "r"(a1), "r"(a2), "r"(a3), "r"(b0), "r"(b1));
}

// ---------------- prep kernels ----------------

__global__ void prep_q(const float* __restrict__ q)
{
    int idx = blockIdx.x * blockDim.x + threadIdx.x;   // B*H*SQ*16
    int d4 = idx & 15;
    int t = idx >> 4;
    int qq = t & (SQ - 1); t >>= 12;
    int h = t % HH, b = t / HH;
    float4 x = *(const float4*)(q + ((size_t)(b * SQ + qq)) * DD + h * DH + 4 * d4);
    uint32_t h0, l0, h1, l1;
    split2(x.x, x.y, h0, l0);
    split2(x.z, x.w, h1, l1);
    size_t o = ((size_t)((b * HH + h) * SQ + qq)) * 32;
    g_QH[o + fragperm(2 * d4)]     = h0;
    g_QH[o + fragperm(2 * d4 + 1)] = h1;
    g_QL[o + fragperm(2 * d4)]     = l0;
    g_QL[o + fragperm(2 * d4 + 1)] = l1;
}

__global__ void prep_k(const float* __restrict__ k)
{
    int idx = blockIdx.x * blockDim.x + threadIdx.x;   // B*H*SKP*16
    int d4 = idx & 15;
    int t = idx >> 4;
    int kk = t & (SKP - 1); t >>= 9;
    int h = t % HH, b = t / HH;
    float4 x = make_float4(0.f, 0.f, 0.f, 0.f);
    if (kk < SK) x = *(const float4*)(k + ((size_t)(b * SK + kk)) * DD + h * DH + 4 * d4);
    uint32_t h0, l0, h1, l1;
    split2(x.x, x.y, h0, l0);
    split2(x.z, x.w, h1, l1);
    size_t o = ((size_t)((b * HH + h) * SKP + kk)) * 32;
    g_KH[o + fragperm(2 * d4)]     = h0;
    g_KH[o + fragperm(2 * d4 + 1)] = h1;
    g_KL[o + fragperm(2 * d4)]     = l0;
    g_KL[o + fragperm(2 * d4 + 1)] = l1;
}

__global__ void prep_v(const float* __restrict__ v)
{
    int idx = blockIdx.x * blockDim.x + threadIdx.x;   // B*H*16*256
    int kp = idx & 255;
    int t = idx >> 8;
    int d4 = t & 15; t >>= 4;
    int h = t % HH, b = t / HH;
    int g0 = 2 * kp, g1 = g0 + 1;
    float4 x0 = make_float4(0.f, 0.f, 0.f, 0.f), x1 = x0;
    if (g0 < SK) x0 = *(const float4*)(v + ((size_t)(b * SK + g0)) * DD + h * DH + 4 * d4);
    if (g1 < SK) x1 = *(const float4*)(v + ((size_t)(b * SK + g1)) * DD + h * DH + 4 * d4);
    float e0[4] = {x0.x, x0.y, x0.z, x0.w};
    float e1[4] = {x1.x, x1.y, x1.z, x1.w};
    int pos = (kp & ~31) + fragperm(kp & 31);
    #pragma unroll
    for (int e = 0; e < 4; e++) {
        int d = 4 * d4 + e;
        uint32_t hi, lo;
        split2(e0[e], e1[e], hi, lo);
        size_t o = ((size_t)((b * HH + h) * DH + d)) * 256 + pos;
        g_VH[o] = hi;
        g_VL[o] = lo;
    }
}

// ---------------- main kernel ----------------

__global__ __launch_bounds__(NTHREADS, 4)
void omost_attn_hmma(const int* __restrict__ mbm,
                     const float* __restrict__ msc,
                     float* __restrict__ outp)
{
    extern __shared__ uint32_t sm[];
    const uint32_t sbase = smem_u32(sm);
    const int tid = threadIdx.x;
    const int w = tid >> 5, lane = tid & 31;
    const int g = lane >> 2, tig = lane & 3;
    const int b = blockIdx.z, h = blockIdx.y, q0 = blockIdx.x * QT;
    const int bh = b * HH + h;

    // ---- stage Q + chunk-0 K/V (raw 16B copies) ----
    #pragma unroll
    for (int i = 0; i < 8; i++) {
        int idx2 = (i & 3) * NTHREADS + tid;
        int r = idx2 >> 3, j = idx2 & 7;
        uint32_t doff = ((i >> 2) ? O_QL : O_QH) + r * STR + 4 * j;
        const uint32_t* src = ((i >> 2) ? g_QL : g_QH) + ((size_t)bh * SQ + q0 + r) * 32 + 4 * j;
        CPA16(sbase + 4 * doff, src);
    }
    #pragma unroll
    for (int i = 0; i < 8; i++) {
        int idx2 = (i & 3) * NTHREADS + tid;
        int r = idx2 >> 3, j = idx2 & 7;
        uint32_t doff = ((i >> 2) ? O_KL : O_KH) + r * STR + 4 * j;
        const uint32_t* src = ((i >> 2) ? g_KL : g_KH) + ((size_t)bh * SKP + r) * 32 + 4 * j;
        CPA16(sbase + 4 * doff, src);
    }
    #pragma unroll
    for (int i = 0; i < 8; i++) {
        int idx2 = (i & 3) * NTHREADS + tid;
        int r = idx2 >> 3, j = idx2 & 7;
        uint32_t doff = ((i >> 2) ? O_VL : O_VH) + r * STR + 4 * j;
        const uint32_t* src = ((i >> 2) ? g_VL : g_VH) + ((size_t)bh * DH + r) * 256 + 4 * j;
        CPA16(sbase + 4 * doff, src);
    }
    CPA_COMMIT();

    float O[8][4];
    #pragma unroll
    for (int n = 0; n < 8; n++)
        #pragma unroll
        for (int j = 0; j < 4; j++) O[n][j] = 0.0f;
    float m0 = MNEG, m1 = MNEG, l0s = 0.0f, l1s = 0.0f;

    const int r0 = 16 * w + g;
    const size_t mrow0 = ((size_t)bh * SQ + q0 + r0) * (size_t)SK;
    const size_t mrow1 = mrow0 + 8 * (size_t)SK;

    for (int c = 0; c < NCH; c++) {
        CPA_WAIT0();
        __syncthreads();

        // ---- QK: S[16 x 64] per warp (bf16x3, LDS.128 fragments) ----
        float S[8][4];
        #pragma unroll
        for (int n = 0; n < 8; n++)
            #pragma unroll
            for (int j = 0; j < 4; j++) S[n][j] = 0.0f;

        #pragma unroll
        for (int sp = 0; sp < 2; sp++) {       // ss pair {2sp, 2sp+1}
            const int fo = tig * 8 + sp * 4;
            uint4 qh0 = *(const uint4*)&sm[O_QH + r0 * STR + fo];
            uint4 qh1 = *(const uint4*)&sm[O_QH + (r0 + 8) * STR + fo];
            uint4 ql0 = *(const uint4*)&sm[O_QL + r0 * STR + fo];
            uint4 ql1 = *(const uint4*)&sm[O_QL + (r0 + 8) * STR + fo];
            #pragma unroll
            for (int n = 0; n < 8; n++) {
                uint4 kh = *(const uint4*)&sm[O_KH + (8 * n + g) * STR + fo];
                uint4 kl = *(const uint4*)&sm[O_KL + (8 * n + g) * STR + fo];
                // ss = 2sp: a0=(r0,w), a1=(r0+8,w), a2=(r0,w+4), a3=(r0+8,w+4)
                mma16816(S[n], qh0.x, qh1.x, qh0.y, qh1.y, kh.x, kh.y);
                mma16816(S[n], ql0.x, ql1.x, ql0.y, ql1.y, kh.x, kh.y);
                mma16816(S[n], qh0.x, qh1.x, qh0.y, qh1.y, kl.x, kl.y);
                // ss = 2sp+1
                mma16816(S[n], qh0.z, qh1.z, qh0.w, qh1.w, kh.z, kh.w);
                mma16816(S[n], ql0.z, ql1.z, ql0.w, ql1.w, kh.z, kh.w);
                mma16816(S[n], qh0.z, qh1.z, qh0.w, qh1.w, kl.z, kl.w);
            }
        }

        // K buffer free -> prefetch next chunk's K
        __syncthreads();
        if (c + 1 < NCH) {
            #pragma unroll
            for (int i = 0; i < 8; i++) {
                int idx2 = (i & 3) * NTHREADS + tid;
                int r = idx2 >> 3, j = idx2 & 7;
                uint32_t doff = ((i >> 2) ? O_KL : O_KH) + r * STR + 4 * j;
                const uint32_t* src = ((i >> 2) ? g_KL : g_KH)
                    + ((size_t)bh * SKP + (c + 1) * CK + r) * 32 + 4 * j;
                CPA16(sbase + 4 * doff, src);
            }
            CPA_COMMIT();
        }

        // ---- mask + scale, chunk row max ----
        float rx0 = MNEG, rx1 = MNEG;
        #pragma unroll
        for (int n = 0; n < 8; n++) {
            int gk = c * CK + 8 * n + 2 * tig;
            if (gk < SK) {
                float2 s0 = *(const float2*)(msc + mrow0 + gk);
                float2 s1 = *(const float2*)(msc + mrow1 + gk);
                int2 b0 = *(const int2*)(mbm + mrow0 + gk);
                int2 b1 = *(const int2*)(mbm + mrow1 + gk);
                S[n][0] = b0.x ? S[n][0] * (0.125f * s0.x) : MNEG;
                S[n][1] = b0.y ? S[n][1] * (0.125f * s0.y) : MNEG;
                S[n][2] = b1.x ? S[n][2] * (0.125f * s1.x) : MNEG;
                S[n][3] = b1.y ? S[n][3] * (0.125f * s1.y) : MNEG;
            } else {
                S[n][0] = MNEG; S[n][1] = MNEG; S[n][2] = MNEG; S[n][3] = MNEG;
            }
            rx0 = fmaxf(rx0, fmaxf(S[n][0], S[n][1]));
            rx1 = fmaxf(rx1, fmaxf(S[n][2], S[n][3]));
        }
        rx0 = fmaxf(rx0, __shfl_xor_sync(0xffffffffu, rx0, 1));
        rx0 = fmaxf(rx0, __shfl_xor_sync(0xffffffffu, rx0, 2));
        rx1 = fmaxf(rx1, __shfl_xor_sync(0xffffffffu, rx1, 1));
        rx1 = fmaxf(rx1, __shfl_xor_sync(0xffffffffu, rx1, 2));

        // ---- online softmax update ----
        float mn0 = fmaxf(m0, rx0), mn1 = fmaxf(m1, rx1);
        float f0 = __expf(m0 - mn0), f1 = __expf(m1 - mn1);
        m0 = mn0; m1 = mn1;
        l0s *= f0; l1s *= f1;
        #pragma unroll
        for (int n = 0; n < 8; n++) {
            O[n][0] *= f0; O[n][1] *= f0;
            O[n][2] *= f1; O[n][3] *= f1;
            S[n][0] = __expf(S[n][0] - m0); l0s += S[n][0];
            S[n][1] = __expf(S[n][1] - m0); l0s += S[n][1];
            S[n][2] = __expf(S[n][2] - m1); l1s += S[n][2];
            S[n][3] = __expf(S[n][3] - m1); l1s += S[n][3];
        }

        // ---- PV: O += P V (bf16x3, LDS.128 fragments) ----
        // ss = 2sp   uses a-frags from S[4sp],   S[4sp+1] with b = (v.x, v.y)
        // ss = 2sp+1 uses a-frags from S[4sp+2], S[4sp+3] with b = (v.z, v.w)
        #pragma unroll
        for (int sp = 0; sp < 2; sp++) {
            const int s0 = 4 * sp;
            uint32_t e0h, e0l, e1h, e1l, e2h, e2l, e3h, e3l;   // ss = 2sp
            uint32_t o0h, o0l, o1h, o1l, o2h, o2l, o3h, o3l;   // ss = 2sp+1
            split2(S[s0][0],     S[s0][1],     e0h, e0l);
            split2(S[s0][2],     S[s0][3],     e1h, e1l);
            split2(S[s0 + 1][0], S[s0 + 1][1], e2h, e2l);
            split2(S[s0 + 1][2], S[s0 + 1][3], e3h, e3l);
            split2(S[s0 + 2][0], S[s0 + 2][1], o0h, o0l);
            split2(S[s0 + 2][2], S[s0 + 2][3], o1h, o1l);
            split2(S[s0 + 3][0], S[s0 + 3][1], o2h, o2l);
            split2(S[s0 + 3][2], S[s0 + 3][3], o3h, o3l);
            const int fo = tig * 8 + sp * 4;
            #pragma unroll
            for (int n = 0; n < 8; n++) {
                uint4 vh = *(const uint4*)&sm[O_VH + (g + 8 * n) * STR + fo];
                uint4 vl = *(const uint4*)&sm[O_VL + (g + 8 * n) * STR + fo];
                mma16816(O[n], e0h, e1h, e2h, e3h, vh.x, vh.y);
                mma16816(O[n], e0l, e1l, e2l, e3l, vh.x, vh.y);
                mma16816(O[n], e0h, e1h, e2h, e3h, vl.x, vl.y);
                mma16816(O[n], o0h, o1h, o2h, o3h, vh.z, vh.w);
                mma16816(O[n], o0l, o1l, o2l, o3l, vh.z, vh.w);
                mma16816(O[n], o0h, o1h, o2h, o3h, vl.z, vl.w);
            }
        }

        // V buffer free -> prefetch next chunk's V
        __syncthreads();
        if (c + 1 < NCH) {
            #pragma unroll
            for (int i = 0; i < 8; i++) {
                int idx2 = (i & 3) * NTHREADS + tid;
                int r = idx2 >> 3, j = idx2 & 7;
                uint32_t doff = ((i >> 2) ? O_VL : O_VH) + r * STR + 4 * j;
                const uint32_t* src = ((i >> 2) ? g_VL : g_VH)
                    + ((size_t)bh * DH + r) * 256 + (c + 1) * 32 + 4 * j;
                CPA16(sbase + 4 * doff, src);
            }
            CPA_COMMIT();
        }
    }

    // ---- finalize ----
    l0s += __shfl_xor_sync(0xffffffffu, l0s, 1);
    l0s += __shfl_xor_sync(0xffffffffu, l0s, 2);
    l1s += __shfl_xor_sync(0xffffffffu, l1s, 1);
    l1s += __shfl_xor_sync(0xffffffffu, l1s, 2);
    const float i0 = 1.0f / l0s, i1 = 1.0f / l1s;

    float* og0 = outp + ((size_t)(b * SQ + q0 + r0)) * DD + h * DH;
    float* og1 = og0 + 8 * (size_t)DD;
    #pragma unroll
    for (int n = 0; n < 8; n++) {
        *(float2*)(og0 + 8 * n + 2 * tig) = make_float2(O[n][0] * i0, O[n][1] * i0);
        *(float2*)(og1 + 8 * n + 2 * tig) = make_float2(O[n][2] * i1, O[n][3] * i1);
    }
}

extern "C" void kernel_launch(void* const* d_in, const int* in_sizes, int n_in,
                              void* d_out, int out_size)
{
    (void)in_sizes; (void)n_in; (void)out_size;
    const float* q  = (const float*)d_in[0];
    const float* k  = (const float*)d_in[1];
    const float* v  = (const float*)d_in[2];
    const int*   mb = (const int*)d_in[3];
    const float* ms = (const float*)d_in[4];
    float* out = (float*)d_out;

    prep_q<<<(BB * HH * SQ * 16) / 256, 256>>>(q);
    prep_k<<<(BB * HH * SKP * 16) / 256, 256>>>(k);
    prep_v<<<(BB * HH * 16 * 256) / 256, 256>>>(v);

    cudaFuncSetAttribute(omost_attn_hmma,
                         cudaFuncAttributeMaxDynamicSharedMemorySize,
                         SMEM_U32 * (int)sizeof(uint32_t));

    dim3 grid(SQ / QT, HH, BB);
    omost_attn_hmma<<<grid, NTHREADS, SMEM_U32 * sizeof(uint32_t)>>>(mb, ms, out);
}

// round 15
// speedup vs baseline: 1.3129x; 1.3129x over previous
#include <cuda_runtime.h>
#include <cuda_bf16.h>
#include <cstdint>

// Problem constants
#define BB 4
#define SQ 4096
#define SK 462
#define SKP 512     // padded
#define HH 10
#define DH 64
#define DD 640

#define QT  64      // q rows per CTA
#define CK  64      // k chunk
#define NCH 8       // chunks (512 padded)
#define NTHREADS 128

#define STR 36      // u32 row stride (rows 144B, 16B-aligned)

// SMEM u32 offsets (six 64x36 buffers)
#define O_QH 0
#define O_QL 2304
#define O_KH 4608
#define O_KL 6912
#define O_VH 9216
#define O_VL 11520
#define SMEM_U32 13824          // 55296 B

#define MNEG (-1e30f)

// Pre-converted bf16 hi/lo buffers, rows permuted into fragment order:
// word w = 8*ss + tig + 4*half  stored at  p = tig*8 + 2*ss + half
__device__ uint32_t g_QH[(size_t)BB*HH*SQ*32];    // [bh][q][32]
__device__ uint32_t g_QL[(size_t)BB*HH*SQ*32];
__device__ uint32_t g_KH[(size_t)BB*HH*SKP*32];   // [bh][kk][32]
__device__ uint32_t g_KL[(size_t)BB*HH*SKP*32];
__device__ uint32_t g_VH[(size_t)BB*HH*DH*256];   // [bh][d][kp] (perm per 32-chunk)
__device__ uint32_t g_VL[(size_t)BB*HH*DH*256];

static __device__ __forceinline__ uint32_t smem_u32(const void* p) {
    uint32_t a;
    asm("{ .reg .u64 t; cvta.to.shared.u64 t, %1; cvt.u32.u64 %0, t; }" : "=r"(a) : "l"(p));
    return a;
}

#define CPA16(dst, src) \
    asm volatile("cp.async.cg.shared.global [%0], [%1], 16;" :: "r"(dst), "l"(src) : "memory")
#define CPA_COMMIT() asm volatile("cp.async.commit_group;" ::: "memory")
#define CPA_WAIT0()  asm volatile("cp.async.wait_group 0;" ::: "memory")

// fragment permutation: w -> p
static __device__ __forceinline__ int fragperm(int w) {
    int ss = w >> 3, rem = w & 7, half = rem >> 2, tig = rem & 3;
    return tig * 8 + ss * 2 + half;
}

static __device__ __forceinline__ void split2(float a, float b,
                                              uint32_t& hi, uint32_t& lo)
{
    __nv_bfloat16 ah = __float2bfloat16_rn(a);
    __nv_bfloat16 bh = __float2bfloat16_rn(b);
    __nv_bfloat16 al = __float2bfloat16_rn(a - __bfloat162float(ah));
    __nv_bfloat16 bl = __float2bfloat16_rn(b - __bfloat162float(bh));
    hi = (uint32_t)__bfloat16_as_ushort(ah) | ((uint32_t)__bfloat16_as_ushort(bh) << 16);
    lo = (uint32_t)__bfloat16_as_ushort(al) | ((uint32_t)__bfloat16_as_ushort(bl) << 16);
}

static __device__ __forceinline__ void mma16816(float* c,
    uint32_t a0, uint32_t a1, uint32_t a2, uint32_t a3, uint32_t b0, uint32_t b1)
{
    asm volatile(
        "mma.sync.aligned.m16n8k16.row.col.f32.bf16.bf16.f32 "
        "{%0,%1,%2,%3}, {%4,%5,%6,%7}, {%8,%9}, {%0,%1,%2,%3};"
        : "+f"(c[0]), "+f"(c[1]), "+f"(c[2]), "+f"(c[3])
        : "r"(a0), "r"(a1), "r"(a2), "r"(a3), "r"(b0), "r"(b1));
}

// ---------------- prep kernels ----------------

__global__ void prep_q(const float* __restrict__ q)
{
    int idx = blockIdx.x * blockDim.x + threadIdx.x;   // B*H*SQ*16
    int d4 = idx & 15;
    int t = idx >> 4;
    int qq = t & (SQ - 1); t >>= 12;
    int h = t % HH, b = t / HH;
    float4 x = *(const float4*)(q + ((size_t)(b * SQ + qq)) * DD + h * DH + 4 * d4);
    uint32_t h0, l0, h1, l1;
    split2(x.x, x.y, h0, l0);
    split2(x.z, x.w, h1, l1);
    size_t o = ((size_t)((b * HH + h) * SQ + qq)) * 32;
    g_QH[o + fragperm(2 * d4)]     = h0;
    g_QH[o + fragperm(2 * d4 + 1)] = h1;
    g_QL[o + fragperm(2 * d4)]     = l0;
    g_QL[o + fragperm(2 * d4 + 1)] = l1;
}

__global__ void prep_k(const float* __restrict__ k)
{
    int idx = blockIdx.x * blockDim.x + threadIdx.x;   // B*H*SKP*16
    int d4 = idx & 15;
    int t = idx >> 4;
    int kk = t & (SKP - 1); t >>= 9;
    int h = t % HH, b = t / HH;
    float4 x = make_float4(0.f, 0.f, 0.f, 0.f);
    if (kk < SK) x = *(const float4*)(k + ((size_t)(b * SK + kk)) * DD + h * DH + 4 * d4);
    uint32_t h0, l0, h1, l1;
    split2(x.x, x.y, h0, l0);
    split2(x.z, x.w, h1, l1);
    size_t o = ((size_t)((b * HH + h) * SKP + kk)) * 32;
    g_KH[o + fragperm(2 * d4)]     = h0;
    g_KH[o + fragperm(2 * d4 + 1)] = h1;
    g_KL[o + fragperm(2 * d4)]     = l0;
    g_KL[o + fragperm(2 * d4 + 1)] = l1;
}

__global__ void prep_v(const float* __restrict__ v)
{
    int idx = blockIdx.x * blockDim.x + threadIdx.x;   // B*H*16*256
    int kp = idx & 255;
    int t = idx >> 8;
    int d4 = t & 15; t >>= 4;
    int h = t % HH, b = t / HH;
    int g0 = 2 * kp, g1 = g0 + 1;
    float4 x0 = make_float4(0.f, 0.f, 0.f, 0.f), x1 = x0;
    if (g0 < SK) x0 = *(const float4*)(v + ((size_t)(b * SK + g0)) * DD + h * DH + 4 * d4);
    if (g1 < SK) x1 = *(const float4*)(v + ((size_t)(b * SK + g1)) * DD + h * DH + 4 * d4);
    float e0[4] = {x0.x, x0.y, x0.z, x0.w};
    float e1[4] = {x1.x, x1.y, x1.z, x1.w};
    int pos = (kp & ~31) + fragperm(kp & 31);
    #pragma unroll
    for (int e = 0; e < 4; e++) {
        int d = 4 * d4 + e;
        uint32_t hi, lo;
        split2(e0[e], e1[e], hi, lo);
        size_t o = ((size_t)((b * HH + h) * DH + d)) * 256 + pos;
        g_VH[o] = hi;
        g_VL[o] = lo;
    }
}

// ---------------- main kernel ----------------

__global__ __launch_bounds__(NTHREADS)
void omost_attn_hmma(const int* __restrict__ mbm,
                     const float* __restrict__ msc,
                     float* __restrict__ outp)
{
    extern __shared__ uint32_t sm[];
    const uint32_t sbase = smem_u32(sm);
    const int tid = threadIdx.x;
    const int w = tid >> 5, lane = tid & 31;
    const int g = lane >> 2, tig = lane & 3;
    const int b = blockIdx.z, h = blockIdx.y, q0 = blockIdx.x * QT;
    const int bh = b * HH + h;

    // ---- stage Q + chunk-0 K/V (raw 16B copies) ----
    #pragma unroll
    for (int i = 0; i < 8; i++) {
        int idx2 = (i & 3) * NTHREADS + tid;
        int r = idx2 >> 3, j = idx2 & 7;
        uint32_t doff = ((i >> 2) ? O_QL : O_QH) + r * STR + 4 * j;
        const uint32_t* src = ((i >> 2) ? g_QL : g_QH) + ((size_t)bh * SQ + q0 + r) * 32 + 4 * j;
        CPA16(sbase + 4 * doff, src);
    }
    #pragma unroll
    for (int i = 0; i < 8; i++) {
        int idx2 = (i & 3) * NTHREADS + tid;
        int r = idx2 >> 3, j = idx2 & 7;
        uint32_t doff = ((i >> 2) ? O_KL : O_KH) + r * STR + 4 * j;
        const uint32_t* src = ((i >> 2) ? g_KL : g_KH) + ((size_t)bh * SKP + r) * 32 + 4 * j;
        CPA16(sbase + 4 * doff, src);
    }
    #pragma unroll
    for (int i = 0; i < 8; i++) {
        int idx2 = (i & 3) * NTHREADS + tid;
        int r = idx2 >> 3, j = idx2 & 7;
        uint32_t doff = ((i >> 2) ? O_VL : O_VH) + r * STR + 4 * j;
        const uint32_t* src = ((i >> 2) ? g_VL : g_VH) + ((size_t)bh * DH + r) * 256 + 4 * j;
        CPA16(sbase + 4 * doff, src);
    }
    CPA_COMMIT();

    float O[8][4];
    #pragma unroll
    for (int n = 0; n < 8; n++)
        #pragma unroll
        for (int j = 0; j < 4; j++) O[n][j] = 0.0f;
    float m0 = MNEG, m1 = MNEG, l0s = 0.0f, l1s = 0.0f;

    const int r0 = 16 * w + g;
    const size_t mrow0 = ((size_t)bh * SQ + q0 + r0) * (size_t)SK;
    const size_t mrow1 = mrow0 + 8 * (size_t)SK;

    for (int c = 0; c < NCH; c++) {
        CPA_WAIT0();
        __syncthreads();

        // ---- QK: S[16 x 64] per warp (bf16x3, LDS.128 fragments) ----
        float S[8][4];
        #pragma unroll
        for (int n = 0; n < 8; n++)
            #pragma unroll
            for (int j = 0; j < 4; j++) S[n][j] = 0.0f;

        #pragma unroll
        for (int sp = 0; sp < 2; sp++) {       // ss pair {2sp, 2sp+1}
            const int fo = tig * 8 + sp * 4;
            uint4 qh0 = *(const uint4*)&sm[O_QH + r0 * STR + fo];
            uint4 qh1 = *(const uint4*)&sm[O_QH + (r0 + 8) * STR + fo];
            uint4 ql0 = *(const uint4*)&sm[O_QL + r0 * STR + fo];
            uint4 ql1 = *(const uint4*)&sm[O_QL + (r0 + 8) * STR + fo];
            #pragma unroll
            for (int n = 0; n < 8; n++) {
                uint4 kh = *(const uint4*)&sm[O_KH + (8 * n + g) * STR + fo];
                uint4 kl = *(const uint4*)&sm[O_KL + (8 * n + g) * STR + fo];
                // ss = 2sp: a0=(r0,w), a1=(r0+8,w), a2=(r0,w+4), a3=(r0+8,w+4)
                mma16816(S[n], qh0.x, qh1.x, qh0.y, qh1.y, kh.x, kh.y);
                mma16816(S[n], ql0.x, ql1.x, ql0.y, ql1.y, kh.x, kh.y);
                mma16816(S[n], qh0.x, qh1.x, qh0.y, qh1.y, kl.x, kl.y);
                // ss = 2sp+1
                mma16816(S[n], qh0.z, qh1.z, qh0.w, qh1.w, kh.z, kh.w);
                mma16816(S[n], ql0.z, ql1.z, ql0.w, ql1.w, kh.z, kh.w);
                mma16816(S[n], qh0.z, qh1.z, qh0.w, qh1.w, kl.z, kl.w);
            }
        }

        // K buffer free -> prefetch next chunk's K
        __syncthreads();
        if (c + 1 < NCH) {
            #pragma unroll
            for (int i = 0; i < 8; i++) {
                int idx2 = (i & 3) * NTHREADS + tid;
                int r = idx2 >> 3, j = idx2 & 7;
                uint32_t doff = ((i >> 2) ? O_KL : O_KH) + r * STR + 4 * j;
                const uint32_t* src = ((i >> 2) ? g_KL : g_KH)
                    + ((size_t)bh * SKP + (c + 1) * CK + r) * 32 + 4 * j;
                CPA16(sbase + 4 * doff, src);
            }
            CPA_COMMIT();
        }

        // ---- mask + scale, chunk row max ----
        float rx0 = MNEG, rx1 = MNEG;
        #pragma unroll
        for (int n = 0; n < 8; n++) {
            int gk = c * CK + 8 * n + 2 * tig;
            if (gk < SK) {
                float2 s0 = *(const float2*)(msc + mrow0 + gk);
                float2 s1 = *(const float2*)(msc + mrow1 + gk);
                int2 b0 = *(const int2*)(mbm + mrow0 + gk);
                int2 b1 = *(const int2*)(mbm + mrow1 + gk);
                S[n][0] = b0.x ? S[n][0] * (0.125f * s0.x) : MNEG;
                S[n][1] = b0.y ? S[n][1] * (0.125f * s0.y) : MNEG;
                S[n][2] = b1.x ? S[n][2] * (0.125f * s1.x) : MNEG;
                S[n][3] = b1.y ? S[n][3] * (0.125f * s1.y) : MNEG;
            } else {
                S[n][0] = MNEG; S[n][1] = MNEG; S[n][2] = MNEG; S[n][3] = MNEG;
            }
            rx0 = fmaxf(rx0, fmaxf(S[n][0], S[n][1]));
            rx1 = fmaxf(rx1, fmaxf(S[n][2], S[n][3]));
        }
        rx0 = fmaxf(rx0, __shfl_xor_sync(0xffffffffu, rx0, 1));
        rx0 = fmaxf(rx0, __shfl_xor_sync(0xffffffffu, rx0, 2));
        rx1 = fmaxf(rx1, __shfl_xor_sync(0xffffffffu, rx1, 1));
        rx1 = fmaxf(rx1, __shfl_xor_sync(0xffffffffu, rx1, 2));

        // ---- online softmax update ----
        float mn0 = fmaxf(m0, rx0), mn1 = fmaxf(m1, rx1);
        float f0 = __expf(m0 - mn0), f1 = __expf(m1 - mn1);
        m0 = mn0; m1 = mn1;
        l0s *= f0; l1s *= f1;
        #pragma unroll
        for (int n = 0; n < 8; n++) {
            O[n][0] *= f0; O[n][1] *= f0;
            O[n][2] *= f1; O[n][3] *= f1;
            S[n][0] = __expf(S[n][0] - m0); l0s += S[n][0];
            S[n][1] = __expf(S[n][1] - m0); l0s += S[n][1];
            S[n][2] = __expf(S[n][2] - m1); l1s += S[n][2];
            S[n][3] = __expf(S[n][3] - m1); l1s += S[n][3];
        }

        // ---- PV: O += P V (bf16x3, LDS.128 fragments) ----
        // ss = 2sp   uses a-frags from S[4sp],   S[4sp+1] with b = (v.x, v.y)
        // ss = 2sp+1 uses a-frags from S[4sp+2], S[4sp+3] with b = (v.z, v.w)
        #pragma unroll
        for (int sp = 0; sp < 2; sp++) {
            const int s0 = 4 * sp;
            uint32_t e0h, e0l, e1h, e1l, e2h, e2l, e3h, e3l;   // ss = 2sp
            uint32_t o0h, o0l, o1h, o1l, o2h, o2l, o3h, o3l;   // ss = 2sp+1
            split2(S[s0][0],     S[s0][1],     e0h, e0l);
            split2(S[s0][2],     S[s0][3],     e1h, e1l);
            split2(S[s0 + 1][0], S[s0 + 1][1], e2h, e2l);
            split2(S[s0 + 1][2], S[s0 + 1][3], e3h, e3l);
            split2(S[s0 + 2][0], S[s0 + 2][1], o0h, o0l);
            split2(S[s0 + 2][2], S[s0 + 2][3], o1h, o1l);
            split2(S[s0 + 3][0], S[s0 + 3][1], o2h, o2l);
            split2(S[s0 + 3][2], S[s0 + 3][3], o3h, o3l);
            const int fo = tig * 8 + sp * 4;
            #pragma unroll
            for (int n = 0; n < 8; n++) {
                uint4 vh = *(const uint4*)&sm[O_VH + (g + 8 * n) * STR + fo];
                uint4 vl = *(const uint4*)&sm[O_VL + (g + 8 * n) * STR + fo];
                mma16816(O[n], e0h, e1h, e2h, e3h, vh.x, vh.y);
                mma16816(O[n], e0l, e1l, e2l, e3l, vh.x, vh.y);
                mma16816(O[n], e0h, e1h, e2h, e3h, vl.x, vl.y);
                mma16816(O[n], o0h, o1h, o2h, o3h, vh.z, vh.w);
                mma16816(O[n], o0l, o1l, o2l, o3l, vh.z, vh.w);
                mma16816(O[n], o0h, o1h, o2h, o3h, vl.z, vl.w);
            }
        }

        // V buffer free -> prefetch next chunk's V
        __syncthreads();
        if (c + 1 < NCH) {
            #pragma unroll
            for (int i = 0; i < 8; i++) {
                int idx2 = (i & 3) * NTHREADS + tid;
                int r = idx2 >> 3, j = idx2 & 7;
                uint32_t doff = ((i >> 2) ? O_VL : O_VH) + r * STR + 4 * j;
                const uint32_t* src = ((i >> 2) ? g_VL : g_VH)
                    + ((size_t)bh * DH + r) * 256 + (c + 1) * 32 + 4 * j;
                CPA16(sbase + 4 * doff, src);
            }
            CPA_COMMIT();
        }
    }

    // ---- finalize ----
    l0s += __shfl_xor_sync(0xffffffffu, l0s, 1);
    l0s += __shfl_xor_sync(0xffffffffu, l0s, 2);
    l1s += __shfl_xor_sync(0xffffffffu, l1s, 1);
    l1s += __shfl_xor_sync(0xffffffffu, l1s, 2);
    const float i0 = 1.0f / l0s, i1 = 1.0f / l1s;

    float* og0 = outp + ((size_t)(b * SQ + q0 + r0)) * DD + h * DH;
    float* og1 = og0 + 8 * (size_t)DD;
    #pragma unroll
    for (int n = 0; n < 8; n++) {
        *(float2*)(og0 + 8 * n + 2 * tig) = make_float2(O[n][0] * i0, O[n][1] * i0);
        *(float2*)(og1 + 8 * n + 2 * tig) = make_float2(O[n][2] * i1, O[n][3] * i1);
    }
}

extern "C" void kernel_launch(void* const* d_in, const int* in_sizes, int n_in,
                              void* d_out, int out_size)
{
    (void)in_sizes; (void)n_in; (void)out_size;
    const float* q  = (const float*)d_in[0];
    const float* k  = (const float*)d_in[1];
    const float* v  = (const float*)d_in[2];
    const int*   mb = (const int*)d_in[3];
    const float* ms = (const float*)d_in[4];
    float* out = (float*)d_out;

    prep_q<<<(BB * HH * SQ * 16) / 256, 256>>>(q);
    prep_k<<<(BB * HH * SKP * 16) / 256, 256>>>(k);
    prep_v<<<(BB * HH * 16 * 256) / 256, 256>>>(v);

    cudaFuncSetAttribute(omost_attn_hmma,
                         cudaFuncAttributeMaxDynamicSharedMemorySize,
                         SMEM_U32 * (int)sizeof(uint32_t));

    dim3 grid(SQ / QT, HH, BB);
    omost_attn_hmma<<<grid, NTHREADS, SMEM_U32 * sizeof(uint32_t)>>>(mb, ms, out);
}

// round 16
// speedup vs baseline: 1.7191x; 1.3094x over previous
#include <cuda_runtime.h>
#include <cuda_bf16.h>
#include <cstdint>

// Problem constants
#define BB 4
#define SQ 4096
#define SK 462
#define SKP 512
#define HH 10
#define DH 64
#define DD 640

#define QT  64
#define CK  64
#define NCH 8
#define NTHREADS 128

#define STR 36      // u32 row stride for Q/K/V buffers

// SMEM u32 offsets
#define O_QH 0
#define O_QL 2304
#define O_KH 4608
#define O_KL 6912
#define O_V0H 9216
#define O_V0L 11520
#define O_V1H 13824
#define O_V1L 16128
#define O_MS 18432          // msc tile: 64 rows x 68 stride (64 used)
#define O_MB 22784          // mbm tile: 64 rows x 68 stride
#define SMEM_U32 27136      // 108544 B -> 2 CTAs/SM

#define MNEG (-1e30f)

// Pre-converted bf16 hi/lo buffers (R11 layout, NO fragment permutation)
__device__ uint32_t g_QH[(size_t)BB*HH*SQ*32];
__device__ uint32_t g_QL[(size_t)BB*HH*SQ*32];
__device__ uint32_t g_KH[(size_t)BB*HH*SKP*32];
__device__ uint32_t g_KL[(size_t)BB*HH*SKP*32];
__device__ uint32_t g_VH[(size_t)BB*HH*DH*256];
__device__ uint32_t g_VL[(size_t)BB*HH*DH*256];

static __device__ __forceinline__ uint32_t smem_u32(const void* p) {
    uint32_t a;
    asm("{ .reg .u64 t; cvta.to.shared.u64 t, %1; cvt.u32.u64 %0, t; }" : "=r"(a) : "l"(p));
    return a;
}

#define CPA16(dst, src) \
    asm volatile("cp.async.cg.shared.global [%0], [%1], 16;" :: "r"(dst), "l"(src) : "memory")
#define CPA8(dst, src) \
    asm volatile("cp.async.ca.shared.global [%0], [%1], 8;" :: "r"(dst), "l"(src) : "memory")
#define CPA_COMMIT() asm volatile("cp.async.commit_group;" ::: "memory")
#define CPA_WAIT0()  asm volatile("cp.async.wait_group 0;" ::: "memory")
#define CPA_WAIT1()  asm volatile("cp.async.wait_group 1;" ::: "memory")

static __device__ __forceinline__ void split2(float a, float b,
                                              uint32_t& hi, uint32_t& lo)
{
    __nv_bfloat16 ah = __float2bfloat16_rn(a);
    __nv_bfloat16 bh = __float2bfloat16_rn(b);
    __nv_bfloat16 al = __float2bfloat16_rn(a - __bfloat162float(ah));
    __nv_bfloat16 bl = __float2bfloat16_rn(b - __bfloat162float(bh));
    hi = (uint32_t)__bfloat16_as_ushort(ah) | ((uint32_t)__bfloat16_as_ushort(bh) << 16);
    lo = (uint32_t)__bfloat16_as_ushort(al) | ((uint32_t)__bfloat16_as_ushort(bl) << 16);
}

static __device__ __forceinline__ void mma16816(float* c,
    uint32_t a0, uint32_t a1, uint32_t a2, uint32_t a3, uint32_t b0, uint32_t b1)
{
    asm volatile(
        "mma.sync.aligned.m16n8k16.row.col.f32.bf16.bf16.f32 "
        "{%0,%1,%2,%3}, {%4,%5,%6,%7}, {%8,%9}, {%0,%1,%2,%3};"
        : "+f"(c[0]), "+f"(c[1]), "+f"(c[2]), "+f"(c[3])
        : "r"(a0), "r"(a1), "r"(a2), "r"(a3), "r"(b0), "r"(b1));
}

// ---------------- prep kernels (R11 versions, no permutation) ----------------

__global__ void prep_q(const float* __restrict__ q)
{
    int idx = blockIdx.x * blockDim.x + threadIdx.x;
    int d4 = idx & 15;
    int t = idx >> 4;
    int qq = t & (SQ - 1); t >>= 12;
    int h = t % HH, b = t / HH;
    float4 x = *(const float4*)(q + ((size_t)(b * SQ + qq)) * DD + h * DH + 4 * d4);
    uint32_t h0, l0, h1, l1;
    split2(x.x, x.y, h0, l0);
    split2(x.z, x.w, h1, l1);
    size_t o = ((size_t)((b * HH + h) * SQ + qq)) * 32 + 2 * d4;
    g_QH[o] = h0; g_QH[o + 1] = h1;
    g_QL[o] = l0; g_QL[o + 1] = l1;
}

__global__ void prep_k(const float* __restrict__ k)
{
    int idx = blockIdx.x * blockDim.x + threadIdx.x;
    int d4 = idx & 15;
    int t = idx >> 4;
    int kk = t & (SKP - 1); t >>= 9;
    int h = t % HH, b = t / HH;
    float4 x = make_float4(0.f, 0.f, 0.f, 0.f);
    if (kk < SK) x = *(const float4*)(k + ((size_t)(b * SK + kk)) * DD + h * DH + 4 * d4);
    uint32_t h0, l0, h1, l1;
    split2(x.x, x.y, h0, l0);
    split2(x.z, x.w, h1, l1);
    size_t o = ((size_t)((b * HH + h) * SKP + kk)) * 32 + 2 * d4;
    g_KH[o] = h0; g_KH[o + 1] = h1;
    g_KL[o] = l0; g_KL[o + 1] = l1;
}

__global__ void prep_v(const float* __restrict__ v)
{
    int idx = blockIdx.x * blockDim.x + threadIdx.x;
    int kp = idx & 255;
    int t = idx >> 8;
    int d4 = t & 15; t >>= 4;
    int h = t % HH, b = t / HH;
    int g0 = 2 * kp, g1 = g0 + 1;
    float4 x0 = make_float4(0.f, 0.f, 0.f, 0.f), x1 = x0;
    if (g0 < SK) x0 = *(const float4*)(v + ((size_t)(b * SK + g0)) * DD + h * DH + 4 * d4);
    if (g1 < SK) x1 = *(const float4*)(v + ((size_t)(b * SK + g1)) * DD + h * DH + 4 * d4);
    float e0[4] = {x0.x, x0.y, x0.z, x0.w};
    float e1[4] = {x1.x, x1.y, x1.z, x1.w};
    #pragma unroll
    for (int e = 0; e < 4; e++) {
        int d = 4 * d4 + e;
        uint32_t hi, lo;
        split2(e0[e], e1[e], hi, lo);
        size_t o = ((size_t)((b * HH + h) * DH + d)) * 256 + kp;
        g_VH[o] = hi;
        g_VL[o] = lo;
    }
}

// ---------------- staging helpers ----------------

static __device__ __forceinline__ void stage_kv(uint32_t sbase, int bh, int cc,
                                                int vbase, int tid)
{
    #pragma unroll
    for (int i = 0; i < 8; i++) {
        int idx2 = (i & 3) * NTHREADS + tid;
        int r = idx2 >> 3, j = idx2 & 7;
        uint32_t doff = ((i >> 2) ? O_KL : O_KH) + r * STR + 4 * j;
        const uint32_t* src = ((i >> 2) ? g_KL : g_KH)
            + ((size_t)bh * SKP + cc * CK + r) * 32 + 4 * j;
        CPA16(sbase + 4 * doff, src);
    }
    #pragma unroll
    for (int i = 0; i < 8; i++) {
        int idx2 = (i & 3) * NTHREADS + tid;
        int r = idx2 >> 3, j = idx2 & 7;
        uint32_t doff = ((i >> 2) ? (vbase + 2304) : vbase) + r * STR + 4 * j;
        const uint32_t* src = ((i >> 2) ? g_VL : g_VH)
            + ((size_t)bh * DH + r) * 256 + cc * 32 + 4 * j;
        CPA16(sbase + 4 * doff, src);
    }
}

static __device__ __forceinline__ void stage_mask(uint32_t sbase,
                                                  const float* mscB,
                                                  const int* mbmB,
                                                  int cc, int tid)
{
    #pragma unroll
    for (int m = 0; m < 16; m++) {
        int unit = m * NTHREADS + tid;     // 0..2047
        int row = unit >> 5, jc = unit & 31;
        CPA8(sbase + 4 * (O_MS + row * 68 + 2 * jc),
             mscB + (size_t)row * SK + cc * 64 + 2 * jc);
        CPA8(sbase + 4 * (O_MB + row * 68 + 2 * jc),
             mbmB + (size_t)row * SK + cc * 64 + 2 * jc);
    }
}

// ---------------- main kernel ----------------

__global__ __launch_bounds__(NTHREADS)
void omost_attn_hmma(const int* __restrict__ mbm,
                     const float* __restrict__ msc,
                     float* __restrict__ outp)
{
    extern __shared__ uint32_t sm[];
    float* smf = reinterpret_cast<float*>(sm);
    const uint32_t sbase = smem_u32(sm);
    const int tid = threadIdx.x;
    const int w = tid >> 5, lane = tid & 31;
    const int g = lane >> 2, tig = lane & 3;
    const int b = blockIdx.z, h = blockIdx.y, q0 = blockIdx.x * QT;
    const int bh = b * HH + h;

    const float* mscB = msc + ((size_t)bh * SQ + q0) * (size_t)SK;
    const int*   mbmB = mbm + ((size_t)bh * SQ + q0) * (size_t)SK;

    // ---- prologue: Q + K(0)/V(0) as group 0, mask(0) as group 1 ----
    #pragma unroll
    for (int i = 0; i < 8; i++) {
        int idx2 = (i & 3) * NTHREADS + tid;
        int r = idx2 >> 3, j = idx2 & 7;
        uint32_t doff = ((i >> 2) ? O_QL : O_QH) + r * STR + 4 * j;
        const uint32_t* src = ((i >> 2) ? g_QL : g_QH)
            + ((size_t)bh * SQ + q0 + r) * 32 + 4 * j;
        CPA16(sbase + 4 * doff, src);
    }
    stage_kv(sbase, bh, 0, O_V0H, tid);
    CPA_COMMIT();
    stage_mask(sbase, mscB, mbmB, 0, tid);
    CPA_COMMIT();

    float O[8][4];
    #pragma unroll
    for (int n = 0; n < 8; n++)
        #pragma unroll
        for (int j = 0; j < 4; j++) O[n][j] = 0.0f;
    float m0 = MNEG, m1 = MNEG, l0s = 0.0f, l1s = 0.0f;

    const int r0 = 16 * w + g;

    for (int c = 0; c < NCH; c++) {
        // K(c)/V(c) ready (mask group may still fly)
        CPA_WAIT1();
        __syncthreads();

        // ---- QK: S[16 x 64] per warp (bf16x3, R11 scalar fragment loads) ----
        float S[8][4];
        #pragma unroll
        for (int n = 0; n < 8; n++)
            #pragma unroll
            for (int j = 0; j < 4; j++) S[n][j] = 0.0f;

        #pragma unroll
        for (int ss = 0; ss < 4; ss++) {
            uint32_t ah0 = sm[O_QH + r0 * STR + 8 * ss + tig];
            uint32_t ah1 = sm[O_QH + (r0 + 8) * STR + 8 * ss + tig];
            uint32_t ah2 = sm[O_QH + r0 * STR + 8 * ss + tig + 4];
            uint32_t ah3 = sm[O_QH + (r0 + 8) * STR + 8 * ss + tig + 4];
            uint32_t al0 = sm[O_QL + r0 * STR + 8 * ss + tig];
            uint32_t al1 = sm[O_QL + (r0 + 8) * STR + 8 * ss + tig];
            uint32_t al2 = sm[O_QL + r0 * STR + 8 * ss + tig + 4];
            uint32_t al3 = sm[O_QL + (r0 + 8) * STR + 8 * ss + tig + 4];
            #pragma unroll
            for (int n = 0; n < 8; n++) {
                uint32_t bh0 = sm[O_KH + (8 * n + g) * STR + 8 * ss + tig];
                uint32_t bh1 = sm[O_KH + (8 * n + g) * STR + 8 * ss + tig + 4];
                uint32_t bl0 = sm[O_KL + (8 * n + g) * STR + 8 * ss + tig];
                uint32_t bl1 = sm[O_KL + (8 * n + g) * STR + 8 * ss + tig + 4];
                mma16816(S[n], ah0, ah1, ah2, ah3, bh0, bh1);
                mma16816(S[n], al0, al1, al2, al3, bh0, bh1);
                mma16816(S[n], ah0, ah1, ah2, ah3, bl0, bl1);
            }
        }

        // K buffer free -> prefetch K(c+1) + V(c+1) (other V buffer) as one group
        __syncthreads();
        if (c + 1 < NCH) {
            stage_kv(sbase, bh, c + 1, ((c + 1) & 1) ? O_V1H : O_V0H, tid);
            CPA_COMMIT();
        }

        // mask(c) ready (K/V(c+1) group keeps flying)
        if (c + 1 < NCH) CPA_WAIT1(); else CPA_WAIT0();
        __syncthreads();

        // ---- mask + scale from SMEM, chunk row max ----
        float rx0 = MNEG, rx1 = MNEG;
        #pragma unroll
        for (int n = 0; n < 8; n++) {
            int lc = 8 * n + 2 * tig;
            int gk = c * CK + lc;
            if (gk < SK) {
                float2 s0 = *(const float2*)&smf[O_MS + r0 * 68 + lc];
                float2 s1 = *(const float2*)&smf[O_MS + (r0 + 8) * 68 + lc];
                int2 b0 = *(const int2*)&sm[O_MB + r0 * 68 + lc];
                int2 b1 = *(const int2*)&sm[O_MB + (r0 + 8) * 68 + lc];
                S[n][0] = b0.x ? S[n][0] * (0.125f * s0.x) : MNEG;
                S[n][1] = b0.y ? S[n][1] * (0.125f * s0.y) : MNEG;
                S[n][2] = b1.x ? S[n][2] * (0.125f * s1.x) : MNEG;
                S[n][3] = b1.y ? S[n][3] * (0.125f * s1.y) : MNEG;
            } else {
                S[n][0] = MNEG; S[n][1] = MNEG; S[n][2] = MNEG; S[n][3] = MNEG;
            }
            rx0 = fmaxf(rx0, fmaxf(S[n][0], S[n][1]));
            rx1 = fmaxf(rx1, fmaxf(S[n][2], S[n][3]));
        }
        rx0 = fmaxf(rx0, __shfl_xor_sync(0xffffffffu, rx0, 1));
        rx0 = fmaxf(rx0, __shfl_xor_sync(0xffffffffu, rx0, 2));
        rx1 = fmaxf(rx1, __shfl_xor_sync(0xffffffffu, rx1, 1));
        rx1 = fmaxf(rx1, __shfl_xor_sync(0xffffffffu, rx1, 2));

        // ---- online softmax update ----
        float mn0 = fmaxf(m0, rx0), mn1 = fmaxf(m1, rx1);
        float f0 = __expf(m0 - mn0), f1 = __expf(m1 - mn1);
        m0 = mn0; m1 = mn1;
        l0s *= f0; l1s *= f1;
        #pragma unroll
        for (int n = 0; n < 8; n++) {
            O[n][0] *= f0; O[n][1] *= f0;
            O[n][2] *= f1; O[n][3] *= f1;
            S[n][0] = __expf(S[n][0] - m0); l0s += S[n][0];
            S[n][1] = __expf(S[n][1] - m0); l0s += S[n][1];
            S[n][2] = __expf(S[n][2] - m1); l1s += S[n][2];
            S[n][3] = __expf(S[n][3] - m1); l1s += S[n][3];
        }

        // mask buffer consumed by ALL warps -> prefetch mask(c+1)
        __syncthreads();
        if (c + 1 < NCH) {
            stage_mask(sbase, mscB, mbmB, c + 1, tid);
            CPA_COMMIT();
        }

        // ---- PV: O += P V (bf16x3, R11 scalar loads from V buffer c&1) ----
        const int vbh = (c & 1) ? O_V1H : O_V0H;
        const int vbl = vbh + 2304;
        #pragma unroll
        for (int ss = 0; ss < 4; ss++) {
            uint32_t ah0, al0, ah1, al1, ah2, al2, ah3, al3;
            split2(S[2 * ss][0],     S[2 * ss][1],     ah0, al0);
            split2(S[2 * ss][2],     S[2 * ss][3],     ah1, al1);
            split2(S[2 * ss + 1][0], S[2 * ss + 1][1], ah2, al2);
            split2(S[2 * ss + 1][2], S[2 * ss + 1][3], ah3, al3);
            #pragma unroll
            for (int n = 0; n < 8; n++) {
                uint32_t bh0 = sm[vbh + (g + 8 * n) * STR + 8 * ss + tig];
                uint32_t bh1 = sm[vbh + (g + 8 * n) * STR + 8 * ss + tig + 4];
                uint32_t bl0 = sm[vbl + (g + 8 * n) * STR + 8 * ss + tig];
                uint32_t bl1 = sm[vbl + (g + 8 * n) * STR + 8 * ss + tig + 4];
                mma16816(O[n], ah0, ah1, ah2, ah3, bh0, bh1);
                mma16816(O[n], al0, al1, al2, al3, bh0, bh1);
                mma16816(O[n], ah0, ah1, ah2, ah3, bl0, bl1);
            }
        }
        // no trailing sync: next loop-top wait+sync guards K/V buffer reuse;
        // V(c) buffer is not written by the in-flight group (double-buffered)
    }

    // ---- finalize ----
    l0s += __shfl_xor_sync(0xffffffffu, l0s, 1);
    l0s += __shfl_xor_sync(0xffffffffu, l0s, 2);
    l1s += __shfl_xor_sync(0xffffffffu, l1s, 1);
    l1s += __shfl_xor_sync(0xffffffffu, l1s, 2);
    const float i0 = 1.0f / l0s, i1 = 1.0f / l1s;

    float* og0 = outp + ((size_t)(b * SQ + q0 + r0)) * DD + h * DH;
    float* og1 = og0 + 8 * (size_t)DD;
    #pragma unroll
    for (int n = 0; n < 8; n++) {
        *(float2*)(og0 + 8 * n + 2 * tig) = make_float2(O[n][0] * i0, O[n][1] * i0);
        *(float2*)(og1 + 8 * n + 2 * tig) = make_float2(O[n][2] * i1, O[n][3] * i1);
    }
}

extern "C" void kernel_launch(void* const* d_in, const int* in_sizes, int n_in,
                              void* d_out, int out_size)
{
    (void)in_sizes; (void)n_in; (void)out_size;
    const float* q  = (const float*)d_in[0];
    const float* k  = (const float*)d_in[1];
    const float* v  = (const float*)d_in[2];
    const int*   mb = (const int*)d_in[3];
    const float* ms = (const float*)d_in[4];
    float* out = (float*)d_out;

    prep_q<<<(BB * HH * SQ * 16) / 256, 256>>>(q);
    prep_k<<<(BB * HH * SKP * 16) / 256, 256>>>(k);
    prep_v<<<(BB * HH * 16 * 256) / 256, 256>>>(v);

    cudaFuncSetAttribute(omost_attn_hmma,
                         cudaFuncAttributeMaxDynamicSharedMemorySize,
                         SMEM_U32 * (int)sizeof(uint32_t));

    dim3 grid(SQ / QT, HH, BB);
    omost_attn_hmma<<<grid, NTHREADS, SMEM_U32 * sizeof(uint32_t)>>>(mb, ms, out);
}